// round 2
// baseline (speedup 1.0000x reference)
#include <cuda_runtime.h>
#include <cstdint>

#define BB 8
#define TT 16
#define NN 1024
#define HH 128
#define NHEADS 8
#define HD 16
#define SNP 4
#define NT 4096
#define EMAX 65536
#define LRELU_SLOPE 0.2f
#define MAXDEG 16

// ---------------- scratch (device globals; no allocation allowed) -------------
__device__ float g_x[BB*TT*NN*HH];       // (B,T,N,H)
__device__ float g_fs[BB*SNP*NN*HH];     // (B,4,N,H) segment input / residual
__device__ float g_feat[BB*NT*HH];       // GAT per-layer features (pre-agg)
__device__ float g_h0[BB*NT*HH];         // layer0 output
__device__ float g_h1[BB*NT*HH];         // layer1 output (+residual)
__device__ float g_el[BB*NT*NHEADS];
__device__ float g_er[BB*NT*NHEADS];
__device__ float g_last[BB*NN*HH];
__device__ float g_stats[BB*2];          // per-batch sum, sumsq
__device__ int   g_deg[NT];
__device__ int   g_cnt[NT];
__device__ int   g_off[NT+1];
__device__ int   g_eid[EMAX];
__device__ int   g_srcs[EMAX];           // CSR-ordered source node ids

// ---------------- f32x2 helpers (FFMA2 path, sm_100+) -------------------------
__device__ __forceinline__ void ffma2(unsigned long long& d, unsigned long long a,
                                      unsigned long long b) {
    asm("fma.rn.f32x2 %0, %1, %2, %0;" : "+l"(d) : "l"(a), "l"(b));
}
__device__ __forceinline__ unsigned long long dup2(float x) {
    unsigned long long v;
    asm("mov.b64 %0, {%1, %2};" : "=l"(v) : "f"(x), "f"(x));
    return v;
}
__device__ __forceinline__ unsigned long long lds64(const float* p) {
    unsigned long long v;
    unsigned a = (unsigned)__cvta_generic_to_shared(p);
    asm("ld.shared.b64 %0, [%1];" : "=l"(v) : "r"(a));
    return v;
}
__device__ __forceinline__ float2 unp2(unsigned long long v) {
    float2 r;
    asm("mov.b64 {%0, %1}, %2;" : "=f"(r.x), "=f"(r.y) : "l"(v));
    return r;
}

// ---------------- CSR build ---------------------------------------------------
__global__ void k_zero() {
    int i = blockIdx.x*blockDim.x + threadIdx.x;
    if (i < NT) { g_deg[i] = 0; g_cnt[i] = 0; }
}

__global__ void k_count(const int* __restrict__ edst, int E) {
    int i = blockIdx.x*blockDim.x + threadIdx.x;
    if (i < E) atomicAdd(&g_deg[edst[i]], 1);
}

__global__ void k_scan() {   // 1 block, 1024 threads, NT=4096
    __shared__ int sh[1024];
    int tid = threadIdx.x;
    int d0 = g_deg[tid*4+0], d1 = g_deg[tid*4+1], d2 = g_deg[tid*4+2], d3 = g_deg[tid*4+3];
    int tot = d0+d1+d2+d3;
    sh[tid] = tot; __syncthreads();
    for (int o = 1; o < 1024; o <<= 1) {
        int v = (tid >= o) ? sh[tid-o] : 0;
        __syncthreads();
        sh[tid] += v;
        __syncthreads();
    }
    int excl = sh[tid] - tot;
    g_off[tid*4+0] = excl;
    g_off[tid*4+1] = excl + d0;
    g_off[tid*4+2] = excl + d0 + d1;
    g_off[tid*4+3] = excl + d0 + d1 + d2;
    if (tid == 1023) g_off[NT] = sh[1023];
}

__global__ void k_fill(const int* __restrict__ edst, int E) {
    int i = blockIdx.x*blockDim.x + threadIdx.x;
    if (i >= E) return;
    int v = edst[i];
    int slot = g_off[v] + atomicAdd(&g_cnt[v], 1);
    g_eid[slot] = i;
}

// deterministic ordering: sort each node's edge ids (deg <= 10)
__global__ void k_sort(const int* __restrict__ esrc) {
    int v = blockIdx.x*blockDim.x + threadIdx.x;
    if (v >= NT) return;
    int o0 = g_off[v];
    int d = g_deg[v]; if (d > MAXDEG) d = MAXDEG;
    for (int i = 1; i < d; i++) {
        int key = g_eid[o0+i];
        int j = i-1;
        while (j >= 0 && g_eid[o0+j] > key) { g_eid[o0+j+1] = g_eid[o0+j]; j--; }
        g_eid[o0+j+1] = key;
    }
    for (int j = 0; j < d; j++) g_srcs[o0+j] = esrc[g_eid[o0+j]];
}

// ---------------- x = inputs@W_in + b_in + spatial + temporal -----------------
__global__ void k_x(const float* __restrict__ in, const float* __restrict__ Win,
                    const float* __restrict__ bin, const float* __restrict__ spat,
                    const float* __restrict__ temp) {
    int idx = blockIdx.x*blockDim.x + threadIdx.x;   // B*T*N*H
    int h = idx & 127;
    int n = (idx >> 7) & 1023;
    int t = (idx >> 17) & 15;
    int b = idx >> 21;
    size_t ib = ((size_t)(b*TT + t)*NN + n)*2;
    float v = in[ib]*Win[h] + in[ib+1]*Win[128+h] + bin[h] + spat[n*128+h] + temp[n*16+t];
    g_x[idx] = v;
}

// ---------------- assemble fs for segment iter, zero stats --------------------
__global__ void k_fs(int iter, int left) {
    int idx = blockIdx.x*blockDim.x + threadIdx.x;   // B*4*N*H
    int h = idx & 127;
    int n = (idx >> 7) & 1023;
    int s = (idx >> 17) & 3;
    int b = idx >> 19;
    float val;
    if (iter > 0 && s == 0) {
        val = g_last[((size_t)b*NN + n)*128 + h];
    } else {
        int t = left + s - (iter > 0 ? 1 : 0);
        val = g_x[(((size_t)b*TT + t)*NN + n)*128 + h];
    }
    g_fs[idx] = val;
    if (idx < 2*BB) g_stats[idx] = 0.f;
}

// ---------------- SGEMM (FFMA2): C[M,128] = A[M,128] @ W[128,128] -------------
// 128x128 tile per block, 256 threads, 8x8 microtile via f32x2, BK=16.
// Fused epilogue computes el/er (per-head dots with al/ar).
__global__ __launch_bounds__(256) void k_gemm(int a_sel, const float* __restrict__ W,
                                              const float* __restrict__ al,
                                              const float* __restrict__ ar) {
    const float* __restrict__ A = a_sel ? g_h0 : g_fs;
    float* __restrict__ C = g_feat;
    __shared__ float As[16][132];
    __shared__ float Bs[16][128];
    int tid = threadIdx.x;
    int block_row = blockIdx.x * 128;
    int tx = tid & 15, ty = tid >> 4;
    unsigned long long acc2[8][4];
    #pragma unroll
    for (int i = 0; i < 8; i++)
        #pragma unroll
        for (int j = 0; j < 4; j++) acc2[i][j] = 0ULL;

    for (int k0 = 0; k0 < 128; k0 += 16) {
        #pragma unroll
        for (int i = 0; i < 2; i++) {
            int f4 = tid*2 + i;            // 0..511
            int r = f4 >> 2;               // 0..127
            int c4 = (f4 & 3) * 4;
            float4 v = *(const float4*)&A[(size_t)(block_row + r)*128 + k0 + c4];
            As[c4+0][r] = v.x; As[c4+1][r] = v.y; As[c4+2][r] = v.z; As[c4+3][r] = v.w;
        }
        #pragma unroll
        for (int i = 0; i < 2; i++) {
            int f4 = tid*2 + i;
            int r = f4 >> 5;               // 0..15
            int c4 = (f4 & 31) * 4;
            *(float4*)&Bs[r][c4] = *(const float4*)&W[(size_t)(k0 + r)*128 + c4];
        }
        __syncthreads();
        #pragma unroll
        for (int k = 0; k < 16; k++) {
            float4 a0 = *(const float4*)&As[k][ty*8];
            float4 a1 = *(const float4*)&As[k][ty*8+4];
            unsigned long long ap[8];
            ap[0]=dup2(a0.x); ap[1]=dup2(a0.y); ap[2]=dup2(a0.z); ap[3]=dup2(a0.w);
            ap[4]=dup2(a1.x); ap[5]=dup2(a1.y); ap[6]=dup2(a1.z); ap[7]=dup2(a1.w);
            unsigned long long bp[4];
            #pragma unroll
            for (int j = 0; j < 4; j++) bp[j] = lds64(&Bs[k][tx*8 + 2*j]);
            #pragma unroll
            for (int i = 0; i < 8; i++)
                #pragma unroll
                for (int j = 0; j < 4; j++) ffma2(acc2[i][j], ap[i], bp[j]);
        }
        __syncthreads();
    }

    // unpack accumulators
    float acc[8][8];
    #pragma unroll
    for (int i = 0; i < 8; i++)
        #pragma unroll
        for (int j = 0; j < 4; j++) {
            float2 v = unp2(acc2[i][j]);
            acc[i][2*j] = v.x; acc[i][2*j+1] = v.y;
        }

    // fused el/er: head = tx>>1, this thread covers cols tx*8..tx*8+7
    int head = tx >> 1;
    int half = (tx & 1) * 8;
    float alr[8], arr[8];
    {
        float4 v0 = *(const float4*)&al[head*16 + half];
        float4 v1 = *(const float4*)&al[head*16 + half + 4];
        alr[0]=v0.x; alr[1]=v0.y; alr[2]=v0.z; alr[3]=v0.w;
        alr[4]=v1.x; alr[5]=v1.y; alr[6]=v1.z; alr[7]=v1.w;
        float4 w0 = *(const float4*)&ar[head*16 + half];
        float4 w1 = *(const float4*)&ar[head*16 + half + 4];
        arr[0]=w0.x; arr[1]=w0.y; arr[2]=w0.z; arr[3]=w0.w;
        arr[4]=w1.x; arr[5]=w1.y; arr[6]=w1.z; arr[7]=w1.w;
    }
    int lane = tid & 31;
    #pragma unroll
    for (int i = 0; i < 8; i++) {
        float pl = 0.f, pr = 0.f;
        #pragma unroll
        for (int j = 0; j < 8; j++) { pl += acc[i][j]*alr[j]; pr += acc[i][j]*arr[j]; }
        pl += __shfl_xor_sync(0xffffffffu, pl, 1);
        pr += __shfl_xor_sync(0xffffffffu, pr, 1);
        if ((lane & 1) == 0) {
            size_t row = (size_t)(block_row + ty*8 + i);
            g_el[row*8 + head] = pl;
            g_er[row*8 + head] = pr;
        }
    }

    // store C
    #pragma unroll
    for (int i = 0; i < 8; i++) {
        size_t r = (size_t)(block_row + ty*8 + i)*128 + tx*8;
        float4 v0 = {acc[i][0], acc[i][1], acc[i][2], acc[i][3]};
        float4 v1 = {acc[i][4], acc[i][5], acc[i][6], acc[i][7]};
        *(float4*)&C[r]   = v0;
        *(float4*)&C[r+4] = v1;
    }
}

// ---------------- fused attention + aggregation: warp per (b, node) -----------
// lanes 0..7 compute per-head softmax; all lanes aggregate (4 dims each).
__global__ __launch_bounds__(256) void k_attn_agg(int layer, const float* __restrict__ bias) {
    int warp = (blockIdx.x * blockDim.x + threadIdx.x) >> 5;
    int lane = threadIdx.x & 31;
    if (warp >= BB*NT) return;
    int v = warp & (NT-1);
    int b = warp >> 12;
    int o0 = g_off[v];
    int d = g_deg[v]; if (d > MAXDEG) d = MAXDEG;

    // each lane < d loads one src id; broadcast to all lanes
    int s_l = (lane < d) ? g_srcs[o0 + lane] : 0;
    int sreg[MAXDEG];
    #pragma unroll
    for (int j = 0; j < MAXDEG; j++) {
        if (j < d) sreg[j] = __shfl_sync(0xffffffffu, s_l, j);
    }

    // attention (lanes 0..7: one head each)
    size_t bNT = (size_t)b*NT;
    float erv = (lane < 8) ? g_er[(bNT + v)*8 + lane] : 0.f;
    float ereg[MAXDEG];
    float m = -1e30f;
    #pragma unroll
    for (int j = 0; j < MAXDEG; j++) {
        if (j < d) {
            float e = 0.f;
            if (lane < 8) {
                e = g_el[(bNT + sreg[j])*8 + lane] + erv;
                e = e > 0.f ? e : LRELU_SLOPE*e;
            }
            ereg[j] = e;
            m = fmaxf(m, e);
        }
    }
    float ssum = 0.f;
    #pragma unroll
    for (int j = 0; j < MAXDEG; j++) {
        if (j < d) { float w = expf(ereg[j]-m); ereg[j] = w; ssum += w; }
    }
    float rinv = 1.0f/ssum;   // lanes>=8 garbage, never read
    #pragma unroll
    for (int j = 0; j < MAXDEG; j++) {
        if (j < d) ereg[j] *= rinv;
    }

    // aggregation: lane covers cols lane*4..lane*4+3; head = lane>>2... cols/16
    float4 acc = make_float4(0.f, 0.f, 0.f, 0.f);
    #pragma unroll
    for (int j = 0; j < MAXDEG; j++) {
        if (j < d) {
            float a = __shfl_sync(0xffffffffu, ereg[j], lane >> 2);
            const float4 f = *(const float4*)&g_feat[(bNT + sreg[j])*128 + lane*4];
            acc.x += a*f.x; acc.y += a*f.y; acc.z += a*f.z; acc.w += a*f.w;
        }
    }
    float4 bv = *(const float4*)&bias[lane*4];
    acc.x += bv.x; acc.y += bv.y; acc.z += bv.z; acc.w += bv.w;
    size_t r = (size_t)warp*128 + lane*4;
    if (layer == 0) {
        acc.x = acc.x > 0.f ? acc.x : expm1f(acc.x);
        acc.y = acc.y > 0.f ? acc.y : expm1f(acc.y);
        acc.z = acc.z > 0.f ? acc.z : expm1f(acc.z);
        acc.w = acc.w > 0.f ? acc.w : expm1f(acc.w);
        *(float4*)&g_h0[r] = acc;
    } else {
        const float4 rv = *(const float4*)&g_fs[r];
        acc.x += rv.x; acc.y += rv.y; acc.z += rv.z; acc.w += rv.w;
        *(float4*)&g_h1[r] = acc;
    }
}

// ---------------- attention pooling over the 4 snapshots + stats --------------
__global__ void k_pool(const float* __restrict__ q) {
    int bn = blockIdx.x;           // b*N + n
    int b = bn >> 10;
    int n = bn & 1023;
    int tid = threadIdx.x;         // 128
    __shared__ float sbuf[128];
    float qv = q[n*128 + tid];
    float xs[4], sc[4];
    #pragma unroll
    for (int t = 0; t < 4; t++)
        xs[t] = g_h1[((size_t)b*NT + t*NN + n)*128 + tid];
    #pragma unroll
    for (int t = 0; t < 4; t++) {
        sbuf[tid] = xs[t]*qv; __syncthreads();
        for (int s = 64; s > 0; s >>= 1) {
            if (tid < s) sbuf[tid] += sbuf[tid+s];
            __syncthreads();
        }
        sc[t] = sbuf[0];
        __syncthreads();
    }
    float m = fmaxf(fmaxf(sc[0], sc[1]), fmaxf(sc[2], sc[3]));
    float e0 = expf(sc[0]-m), e1 = expf(sc[1]-m), e2 = expf(sc[2]-m), e3 = expf(sc[3]-m);
    float rs = 1.0f/(e0+e1+e2+e3);
    float lastv = (e0*xs[0] + e1*xs[1] + e2*xs[2] + e3*xs[3])*rs;
    g_last[(size_t)bn*128 + tid] = lastv;
    // per-batch stats
    sbuf[tid] = lastv; __syncthreads();
    for (int s = 64; s > 0; s >>= 1) { if (tid < s) sbuf[tid] += sbuf[tid+s]; __syncthreads(); }
    if (tid == 0) atomicAdd(&g_stats[b*2], sbuf[0]);
    __syncthreads();
    sbuf[tid] = lastv*lastv; __syncthreads();
    for (int s = 64; s > 0; s >>= 1) { if (tid < s) sbuf[tid] += sbuf[tid+s]; __syncthreads(); }
    if (tid == 0) atomicAdd(&g_stats[b*2+1], sbuf[0]);
}

// ---------------- per-batch layernorm of g_last -------------------------------
__global__ void k_norm() {
    int idx = blockIdx.x*blockDim.x + threadIdx.x;   // B*N*H
    int b = idx >> 17;                                // N*H = 131072
    const float inv = 1.0f/(float)(NN*HH);
    float mu = g_stats[b*2]*inv;
    float var = g_stats[b*2+1]*inv - mu*mu;
    g_last[idx] = (g_last[idx] - mu) * rsqrtf(var + 1e-5f);
}

// ---------------- output head ------------------------------------------------
__global__ void k_out(const float* __restrict__ w1, const float* __restrict__ b1,
                      const float* __restrict__ w2, const float* __restrict__ b2,
                      float* __restrict__ out) {
    int bn = blockIdx.x;           // b*N + n
    int b = bn >> 10;
    int n = bn & 1023;
    int tid = threadIdx.x;         // 128
    __shared__ float sbuf[128];
    float lv = g_last[(size_t)bn*128 + tid];
    float w2v = w2[tid];
    for (int s = 0; s < 12; s++) {
        float t = lv*w1[s] + b1[s];
        t = t > 0.f ? t : 0.f;
        sbuf[tid] = t*w2v; __syncthreads();
        for (int k = 64; k > 0; k >>= 1) {
            if (tid < k) sbuf[tid] += sbuf[tid+k];
            __syncthreads();
        }
        if (tid == 0) out[((size_t)b*12 + s)*NN + n] = sbuf[0] + b2[0];
        __syncthreads();
    }
}

// =============================================================================
extern "C" void kernel_launch(void* const* d_in, const int* in_sizes, int n_in,
                              void* d_out, int out_size) {
    const float* inputs   = (const float*)d_in[0];
    const float* W_in     = (const float*)d_in[1];
    const float* b_in     = (const float*)d_in[2];
    const float* spat     = (const float*)d_in[3];
    const float* temp     = (const float*)d_in[4];
    const float* gat_w0   = (const float*)d_in[5];
    const float* gat_al0  = (const float*)d_in[6];
    const float* gat_ar0  = (const float*)d_in[7];
    const float* gat_b0   = (const float*)d_in[8];
    const float* gat_w1   = (const float*)d_in[9];
    const float* gat_al1  = (const float*)d_in[10];
    const float* gat_ar1  = (const float*)d_in[11];
    const float* gat_b1   = (const float*)d_in[12];
    const float* agg_q    = (const float*)d_in[13];
    const float* w_out1   = (const float*)d_in[14];
    const float* b_out1   = (const float*)d_in[15];
    const float* w_out2   = (const float*)d_in[16];
    const float* b_out2   = (const float*)d_in[17];
    const int*   esrc     = (const int*)d_in[18];
    const int*   edst     = (const int*)d_in[19];
    int E = in_sizes[18];

    // CSR build (same inputs every call -> deterministic; per-node sort fixes order)
    k_zero<<<(NT+255)/256, 256>>>();
    k_count<<<(E+255)/256, 256>>>(edst, E);
    k_scan<<<1, 1024>>>();
    k_fill<<<(E+255)/256, 256>>>(edst, E);
    k_sort<<<(NT+127)/128, 128>>>(esrc);

    // x
    k_x<<<(BB*TT*NN*HH)/256, 256>>>(inputs, W_in, b_in, spat, temp);

    const int lefts[5] = {0, 4, 7, 10, 13};
    for (int it = 0; it < 5; it++) {
        k_fs<<<(BB*SNP*NN*HH)/256, 256>>>(it, lefts[it]);
        // GAT layer 0
        k_gemm<<<(BB*NT)/128, 256>>>(0, gat_w0, gat_al0, gat_ar0);
        k_attn_agg<<<(BB*NT)/8, 256>>>(0, gat_b0);
        // GAT layer 1
        k_gemm<<<(BB*NT)/128, 256>>>(1, gat_w1, gat_al1, gat_ar1);
        k_attn_agg<<<(BB*NT)/8, 256>>>(1, gat_b1);
        // pool + layernorm
        k_pool<<<BB*NN, 128>>>(agg_q);
        k_norm<<<(BB*NN*HH)/256, 256>>>();
    }

    k_out<<<BB*NN, 128>>>(w_out1, b_out1, w_out2, b_out2, (float*)d_out);
}

// round 3
// speedup vs baseline: 1.2013x; 1.2013x over previous
#include <cuda_runtime.h>
#include <cuda_bf16.h>
#include <cstdint>

#define BB 8
#define TT 16
#define NN 1024
#define HH 128
#define NHEADS 8
#define SNP 4
#define NT 4096
#define EMAX 65536
#define LRELU_SLOPE 0.2f
#define MAXDEG 16

// ---------------- scratch (device globals) ------------------------------------
__device__ float g_x[BB*TT*NN*HH];       // (B,T,N,H)
__device__ float g_feat[BB*NT*HH];       // GAT per-layer features (pre-agg)
__device__ float g_h0[BB*NT*HH];         // layer0 output
__device__ float g_h1[BB*NT*HH];         // layer1 output (+residual)
__device__ float g_el[BB*NT*NHEADS];
__device__ float g_er[BB*NT*NHEADS];
__device__ float g_last[BB*NN*HH];
__device__ float g_stats[BB*2];
__device__ int   g_deg[NT];
__device__ int   g_cnt[NT];
__device__ int   g_off[NT+1];
__device__ int   g_eid[EMAX];
__device__ int   g_srcs[EMAX];
__device__ __nv_bfloat16 g_wthi[2][HH*HH];   // W^T hi, [n][k]
__device__ __nv_bfloat16 g_wtlo[2][HH*HH];   // W^T lo

// ---------------- helpers ------------------------------------------------------
__device__ __forceinline__ unsigned packbf(float x, float y) {
    __nv_bfloat162 t = __floats2bfloat162_rn(x, y);
    return *(unsigned*)&t;
}
__device__ __forceinline__ void mma16816(float* c, unsigned a0, unsigned a1,
                                         unsigned a2, unsigned a3,
                                         unsigned b0, unsigned b1) {
    asm volatile(
        "mma.sync.aligned.m16n8k16.row.col.f32.bf16.bf16.f32 "
        "{%0,%1,%2,%3},{%4,%5,%6,%7},{%8,%9},{%0,%1,%2,%3};\n"
        : "+f"(c[0]), "+f"(c[1]), "+f"(c[2]), "+f"(c[3])
        : "r"(a0), "r"(a1), "r"(a2), "r"(a3), "r"(b0), "r"(b1));
}
// fs row source: segment input assembled on the fly (replaces old k_fs/g_fs)
__device__ __forceinline__ const float* fs_row(int row, int iter, int left) {
    int b = row >> 12, s = (row >> 10) & 3, n = row & 1023;
    if (iter > 0 && s == 0) return &g_last[((size_t)(b*NN + n))*HH];
    int t = left + s - (iter > 0 ? 1 : 0);
    return &g_x[((size_t)((b*TT + t)*NN + n))*HH];
}

// ---------------- weight conversion (once per call) ---------------------------
__global__ void k_wconv(const float* __restrict__ W0, const float* __restrict__ W1) {
    int id = blockIdx.x*blockDim.x + threadIdx.x;   // 2*128*128
    if (id >= 2*HH*HH) return;
    int layer = id >> 14;
    int r = id & 16383;
    int k = r >> 7, n = r & 127;
    float w = (layer ? W1 : W0)[k*HH + n];
    __nv_bfloat16 hi = __float2bfloat16_rn(w);
    __nv_bfloat16 lo = __float2bfloat16_rn(w - __bfloat162float(hi));
    g_wthi[layer][n*HH + k] = hi;
    g_wtlo[layer][n*HH + k] = lo;
}

// ---------------- CSR build ---------------------------------------------------
__global__ void k_zero() {
    int i = blockIdx.x*blockDim.x + threadIdx.x;
    if (i < NT) { g_deg[i] = 0; g_cnt[i] = 0; }
}
__global__ void k_count(const int* __restrict__ edst, int E) {
    int i = blockIdx.x*blockDim.x + threadIdx.x;
    if (i < E) atomicAdd(&g_deg[edst[i]], 1);
}
__global__ void k_scan() {
    __shared__ int sh[1024];
    int tid = threadIdx.x;
    int d0 = g_deg[tid*4+0], d1 = g_deg[tid*4+1], d2 = g_deg[tid*4+2], d3 = g_deg[tid*4+3];
    int tot = d0+d1+d2+d3;
    sh[tid] = tot; __syncthreads();
    for (int o = 1; o < 1024; o <<= 1) {
        int v = (tid >= o) ? sh[tid-o] : 0;
        __syncthreads();
        sh[tid] += v;
        __syncthreads();
    }
    int excl = sh[tid] - tot;
    g_off[tid*4+0] = excl;
    g_off[tid*4+1] = excl + d0;
    g_off[tid*4+2] = excl + d0 + d1;
    g_off[tid*4+3] = excl + d0 + d1 + d2;
    if (tid == 1023) g_off[NT] = sh[1023];
}
__global__ void k_fill(const int* __restrict__ edst, int E) {
    int i = blockIdx.x*blockDim.x + threadIdx.x;
    if (i >= E) return;
    int v = edst[i];
    int slot = g_off[v] + atomicAdd(&g_cnt[v], 1);
    g_eid[slot] = i;
}
__global__ void k_sort(const int* __restrict__ esrc) {
    int v = blockIdx.x*blockDim.x + threadIdx.x;
    if (v >= NT) return;
    int o0 = g_off[v];
    int d = g_deg[v]; if (d > MAXDEG) d = MAXDEG;
    for (int i = 1; i < d; i++) {
        int key = g_eid[o0+i];
        int j = i-1;
        while (j >= 0 && g_eid[o0+j] > key) { g_eid[o0+j+1] = g_eid[o0+j]; j--; }
        g_eid[o0+j+1] = key;
    }
    for (int j = 0; j < d; j++) g_srcs[o0+j] = esrc[g_eid[o0+j]];
}

// ---------------- x = inputs@W_in + b_in + spatial + temporal -----------------
__global__ void k_x(const float* __restrict__ in, const float* __restrict__ Win,
                    const float* __restrict__ bin, const float* __restrict__ spat,
                    const float* __restrict__ temp) {
    int idx = blockIdx.x*blockDim.x + threadIdx.x;
    int h = idx & 127;
    int n = (idx >> 7) & 1023;
    int t = (idx >> 17) & 15;
    int b = idx >> 21;
    size_t ib = ((size_t)(b*TT + t)*NN + n)*2;
    float v = in[ib]*Win[h] + in[ib+1]*Win[128+h] + bin[h] + spat[n*128+h] + temp[n*16+t];
    g_x[idx] = v;
}

// ---------------- MMA GEMM (bf16 split): C = A @ W, fused el/er ---------------
// 128x128 tile per block, 256 threads (8 warps), warp = 16 rows x full N.
#define AP 20
#define BP 18
__global__ __launch_bounds__(256, 2) void k_gemm(int layer, int iter, int left,
                                                 const float* __restrict__ al,
                                                 const float* __restrict__ ar) {
    __shared__ __nv_bfloat16 sAh[128*AP], sAl[128*AP];
    __shared__ __nv_bfloat16 sBh[128*BP], sBl[128*BP];
    __shared__ float s_al[128], s_ar[128];
    int tid = threadIdx.x;
    int lane = tid & 31, warp = tid >> 5;
    int block_row = blockIdx.x * 128;

    if (layer == 0 && blockIdx.x == 0 && tid < 2*BB) g_stats[tid] = 0.f;
    if (tid < 128) { s_al[tid] = al[tid]; s_ar[tid] = ar[tid]; }

    float acc[16][4];
    #pragma unroll
    for (int nt = 0; nt < 16; nt++)
        #pragma unroll
        for (int j = 0; j < 4; j++) acc[nt][j] = 0.f;

    const __nv_bfloat16* wthi = g_wthi[layer];
    const __nv_bfloat16* wtlo = g_wtlo[layer];

    for (int kc = 0; kc < 8; kc++) {
        int k0 = kc * 16;
        // stage A (fp32 -> hi/lo bf16)
        #pragma unroll
        for (int i = 0; i < 2; i++) {
            int q = tid*2 + i;            // 0..511
            int row = q >> 2;
            int kq = (q & 3) * 4;
            const float* src;
            if (layer == 0) src = fs_row(block_row + row, iter, left) + k0 + kq;
            else            src = &g_h0[((size_t)(block_row + row))*HH + k0 + kq];
            float4 v = *(const float4*)src;
            __nv_bfloat16 h0 = __float2bfloat16_rn(v.x);
            __nv_bfloat16 h1 = __float2bfloat16_rn(v.y);
            __nv_bfloat16 h2 = __float2bfloat16_rn(v.z);
            __nv_bfloat16 h3 = __float2bfloat16_rn(v.w);
            float l0 = v.x - __bfloat162float(h0);
            float l1 = v.y - __bfloat162float(h1);
            float l2 = v.z - __bfloat162float(h2);
            float l3 = v.w - __bfloat162float(h3);
            int base = row*AP + kq;
            *(unsigned*)&sAh[base]   = ((unsigned)__bfloat16_as_ushort(h1) << 16) | __bfloat16_as_ushort(h0);
            *(unsigned*)&sAh[base+2] = ((unsigned)__bfloat16_as_ushort(h3) << 16) | __bfloat16_as_ushort(h2);
            *(unsigned*)&sAl[base]   = packbf(l0, l1);
            *(unsigned*)&sAl[base+2] = packbf(l2, l3);
        }
        // stage B (copy bf16 Wt chunk)
        #pragma unroll
        for (int i = 0; i < 2; i++) {
            int c = tid*2 + i;            // 0..511 chunks of 4 bf16
            int n = c >> 2;
            int kq = (c & 3) * 4;
            uint2 wh = *(const uint2*)&wthi[n*HH + k0 + kq];
            uint2 wl = *(const uint2*)&wtlo[n*HH + k0 + kq];
            int base = n*BP + kq;
            *(unsigned*)&sBh[base]   = wh.x;
            *(unsigned*)&sBh[base+2] = wh.y;
            *(unsigned*)&sBl[base]   = wl.x;
            *(unsigned*)&sBl[base+2] = wl.y;
        }
        __syncthreads();

        int rowb = warp*16 + (lane >> 2);
        int kp = (lane & 3) * 2;
        unsigned ah0 = *(const unsigned*)&sAh[rowb*AP + kp];
        unsigned ah1 = *(const unsigned*)&sAh[(rowb+8)*AP + kp];
        unsigned ah2 = *(const unsigned*)&sAh[rowb*AP + kp + 8];
        unsigned ah3 = *(const unsigned*)&sAh[(rowb+8)*AP + kp + 8];
        unsigned al0 = *(const unsigned*)&sAl[rowb*AP + kp];
        unsigned al1 = *(const unsigned*)&sAl[(rowb+8)*AP + kp];
        unsigned al2 = *(const unsigned*)&sAl[rowb*AP + kp + 8];
        unsigned al3 = *(const unsigned*)&sAl[(rowb+8)*AP + kp + 8];
        #pragma unroll
        for (int nt = 0; nt < 16; nt++) {
            int nb = nt*8 + (lane >> 2);
            unsigned bh0 = *(const unsigned*)&sBh[nb*BP + kp];
            unsigned bh1 = *(const unsigned*)&sBh[nb*BP + kp + 8];
            unsigned bl0 = *(const unsigned*)&sBl[nb*BP + kp];
            unsigned bl1 = *(const unsigned*)&sBl[nb*BP + kp + 8];
            mma16816(acc[nt], ah0, ah1, ah2, ah3, bh0, bh1);
            mma16816(acc[nt], ah0, ah1, ah2, ah3, bl0, bl1);
            mma16816(acc[nt], al0, al1, al2, al3, bh0, bh1);
        }
        __syncthreads();
    }

    // epilogue: store C + fused el/er
    int r0 = block_row + warp*16 + (lane >> 2);
    int r8 = r0 + 8;
    float pl0[8], pl8[8], pr0[8], pr8[8];
    #pragma unroll
    for (int h = 0; h < 8; h++) { pl0[h]=0.f; pl8[h]=0.f; pr0[h]=0.f; pr8[h]=0.f; }
    #pragma unroll
    for (int nt = 0; nt < 16; nt++) {
        int c = nt*8 + (lane & 3)*2;
        int h = nt >> 1;
        float a0 = s_al[c], a1 = s_al[c+1];
        float b0 = s_ar[c], b1 = s_ar[c+1];
        pl0[h] += acc[nt][0]*a0 + acc[nt][1]*a1;
        pr0[h] += acc[nt][0]*b0 + acc[nt][1]*b1;
        pl8[h] += acc[nt][2]*a0 + acc[nt][3]*a1;
        pr8[h] += acc[nt][2]*b0 + acc[nt][3]*b1;
        float2 v0 = {acc[nt][0], acc[nt][1]};
        float2 v1 = {acc[nt][2], acc[nt][3]};
        *(float2*)&g_feat[(size_t)r0*HH + c] = v0;
        *(float2*)&g_feat[(size_t)r8*HH + c] = v1;
    }
    #pragma unroll
    for (int h = 0; h < 8; h++) {
        pl0[h] += __shfl_xor_sync(0xffffffffu, pl0[h], 1);
        pl0[h] += __shfl_xor_sync(0xffffffffu, pl0[h], 2);
        pl8[h] += __shfl_xor_sync(0xffffffffu, pl8[h], 1);
        pl8[h] += __shfl_xor_sync(0xffffffffu, pl8[h], 2);
        pr0[h] += __shfl_xor_sync(0xffffffffu, pr0[h], 1);
        pr0[h] += __shfl_xor_sync(0xffffffffu, pr0[h], 2);
        pr8[h] += __shfl_xor_sync(0xffffffffu, pr8[h], 1);
        pr8[h] += __shfl_xor_sync(0xffffffffu, pr8[h], 2);
    }
    if ((lane & 3) == 0) {
        #pragma unroll
        for (int h = 0; h < 8; h++) {
            g_el[(size_t)r0*8 + h] = pl0[h];
            g_el[(size_t)r8*8 + h] = pl8[h];
            g_er[(size_t)r0*8 + h] = pr0[h];
            g_er[(size_t)r8*8 + h] = pr8[h];
        }
    }
}

// ---------------- fused attention + aggregation: warp per (b, node) -----------
__global__ __launch_bounds__(256) void k_attn_agg(int layer, const float* __restrict__ bias,
                                                  int iter, int left) {
    int warp = (blockIdx.x * blockDim.x + threadIdx.x) >> 5;
    int lane = threadIdx.x & 31;
    if (warp >= BB*NT) return;
    int v = warp & (NT-1);
    int b = warp >> 12;
    int o0 = g_off[v];
    int d = g_deg[v]; if (d > MAXDEG) d = MAXDEG;

    int s_l = (lane < d) ? g_srcs[o0 + lane] : 0;
    int sreg[MAXDEG];
    #pragma unroll
    for (int j = 0; j < MAXDEG; j++) {
        if (j < d) sreg[j] = __shfl_sync(0xffffffffu, s_l, j);
    }

    size_t bNT = (size_t)b*NT;
    float erv = (lane < 8) ? g_er[(bNT + v)*8 + lane] : 0.f;
    float ereg[MAXDEG];
    float m = -1e30f;
    #pragma unroll
    for (int j = 0; j < MAXDEG; j++) {
        if (j < d) {
            float e = 0.f;
            if (lane < 8) {
                e = g_el[(bNT + sreg[j])*8 + lane] + erv;
                e = e > 0.f ? e : LRELU_SLOPE*e;
            }
            ereg[j] = e;
            m = fmaxf(m, e);
        }
    }
    float ssum = 0.f;
    #pragma unroll
    for (int j = 0; j < MAXDEG; j++) {
        if (j < d) { float w = expf(ereg[j]-m); ereg[j] = w; ssum += w; }
    }
    float rinv = 1.0f/ssum;
    #pragma unroll
    for (int j = 0; j < MAXDEG; j++) {
        if (j < d) ereg[j] *= rinv;
    }

    float4 acc = make_float4(0.f, 0.f, 0.f, 0.f);
    #pragma unroll
    for (int j = 0; j < MAXDEG; j++) {
        if (j < d) {
            float a = __shfl_sync(0xffffffffu, ereg[j], lane >> 2);
            const float4 f = *(const float4*)&g_feat[(bNT + sreg[j])*128 + lane*4];
            acc.x += a*f.x; acc.y += a*f.y; acc.z += a*f.z; acc.w += a*f.w;
        }
    }
    float4 bv = *(const float4*)&bias[lane*4];
    acc.x += bv.x; acc.y += bv.y; acc.z += bv.z; acc.w += bv.w;
    size_t r = (size_t)warp*128 + lane*4;
    if (layer == 0) {
        acc.x = acc.x > 0.f ? acc.x : expm1f(acc.x);
        acc.y = acc.y > 0.f ? acc.y : expm1f(acc.y);
        acc.z = acc.z > 0.f ? acc.z : expm1f(acc.z);
        acc.w = acc.w > 0.f ? acc.w : expm1f(acc.w);
        *(float4*)&g_h0[r] = acc;
    } else {
        const float4 rv = *(const float4*)(fs_row(warp, iter, left) + lane*4);
        acc.x += rv.x; acc.y += rv.y; acc.z += rv.z; acc.w += rv.w;
        *(float4*)&g_h1[r] = acc;
    }
}

// ---------------- attention pooling (shuffle reductions) ----------------------
__global__ void k_pool(const float* __restrict__ q) {
    int bn = blockIdx.x;
    int b = bn >> 10;
    int n = bn & 1023;
    int tid = threadIdx.x;         // 128
    int lane = tid & 31, w = tid >> 5;
    __shared__ float sred[16];
    __shared__ float s2[8];
    float qv = q[n*128 + tid];
    float xs[4], p[4];
    #pragma unroll
    for (int t = 0; t < 4; t++) {
        xs[t] = g_h1[((size_t)b*NT + t*NN + n)*128 + tid];
        p[t] = xs[t]*qv;
    }
    #pragma unroll
    for (int t = 0; t < 4; t++) {
        #pragma unroll
        for (int o = 16; o > 0; o >>= 1) p[t] += __shfl_xor_sync(0xffffffffu, p[t], o);
    }
    if (lane == 0) {
        #pragma unroll
        for (int t = 0; t < 4; t++) sred[w*4+t] = p[t];
    }
    __syncthreads();
    float sc[4];
    #pragma unroll
    for (int t = 0; t < 4; t++) sc[t] = sred[t] + sred[4+t] + sred[8+t] + sred[12+t];
    float m = fmaxf(fmaxf(sc[0], sc[1]), fmaxf(sc[2], sc[3]));
    float e0 = expf(sc[0]-m), e1 = expf(sc[1]-m), e2 = expf(sc[2]-m), e3 = expf(sc[3]-m);
    float rs = 1.0f/(e0+e1+e2+e3);
    float lastv = (e0*xs[0] + e1*xs[1] + e2*xs[2] + e3*xs[3])*rs;
    g_last[(size_t)bn*128 + tid] = lastv;
    float s1v = lastv, s2v = lastv*lastv;
    #pragma unroll
    for (int o = 16; o > 0; o >>= 1) {
        s1v += __shfl_xor_sync(0xffffffffu, s1v, o);
        s2v += __shfl_xor_sync(0xffffffffu, s2v, o);
    }
    if (lane == 0) { s2[w] = s1v; s2[4+w] = s2v; }
    __syncthreads();
    if (tid == 0) atomicAdd(&g_stats[b*2],   s2[0]+s2[1]+s2[2]+s2[3]);
    if (tid == 1) atomicAdd(&g_stats[b*2+1], s2[4]+s2[5]+s2[6]+s2[7]);
}

// ---------------- per-batch layernorm of g_last -------------------------------
__global__ void k_norm() {
    int idx = blockIdx.x*blockDim.x + threadIdx.x;
    int b = idx >> 17;
    const float inv = 1.0f/(float)(NN*HH);
    float mu = g_stats[b*2]*inv;
    float var = g_stats[b*2+1]*inv - mu*mu;
    g_last[idx] = (g_last[idx] - mu) * rsqrtf(var + 1e-5f);
}

// ---------------- output head (shuffle reductions) ----------------------------
__global__ void k_out(const float* __restrict__ w1, const float* __restrict__ b1,
                      const float* __restrict__ w2, const float* __restrict__ b2,
                      float* __restrict__ out) {
    int bn = blockIdx.x;
    int b = bn >> 10;
    int n = bn & 1023;
    int tid = threadIdx.x;         // 128
    int lane = tid & 31, w = tid >> 5;
    __shared__ float sred[4][12];
    float lv = g_last[(size_t)bn*128 + tid];
    float w2v = w2[tid];
    float p[12];
    #pragma unroll
    for (int s = 0; s < 12; s++) {
        float t = lv*w1[s] + b1[s];
        t = t > 0.f ? t : 0.f;
        p[s] = t*w2v;
    }
    #pragma unroll
    for (int s = 0; s < 12; s++) {
        #pragma unroll
        for (int o = 16; o > 0; o >>= 1) p[s] += __shfl_xor_sync(0xffffffffu, p[s], o);
    }
    if (lane == 0) {
        #pragma unroll
        for (int s = 0; s < 12; s++) sred[w][s] = p[s];
    }
    __syncthreads();
    if (tid < 12)
        out[((size_t)b*12 + tid)*NN + n] = sred[0][tid]+sred[1][tid]+sred[2][tid]+sred[3][tid] + b2[0];
}

// =============================================================================
extern "C" void kernel_launch(void* const* d_in, const int* in_sizes, int n_in,
                              void* d_out, int out_size) {
    const float* inputs   = (const float*)d_in[0];
    const float* W_in     = (const float*)d_in[1];
    const float* b_in     = (const float*)d_in[2];
    const float* spat     = (const float*)d_in[3];
    const float* temp     = (const float*)d_in[4];
    const float* gat_w0   = (const float*)d_in[5];
    const float* gat_al0  = (const float*)d_in[6];
    const float* gat_ar0  = (const float*)d_in[7];
    const float* gat_b0   = (const float*)d_in[8];
    const float* gat_w1   = (const float*)d_in[9];
    const float* gat_al1  = (const float*)d_in[10];
    const float* gat_ar1  = (const float*)d_in[11];
    const float* gat_b1   = (const float*)d_in[12];
    const float* agg_q    = (const float*)d_in[13];
    const float* w_out1   = (const float*)d_in[14];
    const float* b_out1   = (const float*)d_in[15];
    const float* w_out2   = (const float*)d_in[16];
    const float* b_out2   = (const float*)d_in[17];
    const int*   esrc     = (const int*)d_in[18];
    const int*   edst     = (const int*)d_in[19];
    int E = in_sizes[18];

    const int lefts[5] = {0, 4, 7, 10, 13};

    // order chosen so launch index 3 (the slot ncu captures) is a GEMM
    k_wconv<<<(2*HH*HH+255)/256, 256>>>(gat_w0, gat_w1);                 // 0
    k_x<<<(BB*TT*NN*HH)/256, 256>>>(inputs, W_in, b_in, spat, temp);     // 1
    k_zero<<<(NT+255)/256, 256>>>();                                     // 2
    k_gemm<<<(BB*NT)/128, 256>>>(0, 0, 0, gat_al0, gat_ar0);             // 3 <- profiled
    k_count<<<(E+255)/256, 256>>>(edst, E);                              // 4
    k_scan<<<1, 1024>>>();                                               // 5
    k_fill<<<(E+255)/256, 256>>>(edst, E);                               // 6
    k_sort<<<(NT+127)/128, 128>>>(esrc);                                 // 7

    for (int it = 0; it < 5; it++) {
        if (it > 0)
            k_gemm<<<(BB*NT)/128, 256>>>(0, it, lefts[it], gat_al0, gat_ar0);
        k_attn_agg<<<(BB*NT)/8, 256>>>(0, gat_b0, it, lefts[it]);
        k_gemm<<<(BB*NT)/128, 256>>>(1, it, lefts[it], gat_al1, gat_ar1);
        k_attn_agg<<<(BB*NT)/8, 256>>>(1, gat_b1, it, lefts[it]);
        k_pool<<<BB*NN, 128>>>(agg_q);
        k_norm<<<(BB*NN*HH)/256, 256>>>();
    }

    k_out<<<BB*NN, 128>>>(w_out1, b_out1, w_out2, b_out2, (float*)d_out);
}